// round 3
// baseline (speedup 1.0000x reference)
#include <cuda_runtime.h>
#include <math.h>

#define BB 2
#define LL 2048
#define DD 512
#define HH 8
#define DHH 64
#define BHH (BB*HH)

// Scratch (allocation-free rule: __device__ globals, referenced directly
// from device code — no cudaGetSymbolAddress on the host).
__device__ float g_qh[BHH*LL*DHH];
__device__ float g_kh[BHH*LL*DHH];
__device__ float g_vh[BHH*LL*DHH];
__device__ float g_ctx[BB*LL*DD];

// ---------------------------------------------------------------------------
// GEMM: Y = X @ W^T + bias.  X: 4096 x 512, W: 512 x 512 row-major.
// MODE 0: X from param, scatter into g_qh/g_kh/g_vh per `which`
// MODE 1: X = g_ctx (device global), plain row-major into Y
// Tile 128x64, BK=32, 256 threads, 8x4 micro-tile per thread.
// ---------------------------------------------------------------------------
template<int MODE>
__global__ __launch_bounds__(256) void gemm_bias_kernel(
    const float* __restrict__ Xin, const float* __restrict__ W,
    const float* __restrict__ bias, float* __restrict__ Yout, int which)
{
    __shared__ float Xs[128*33];
    __shared__ float Ws[64*33];
    const int tid = threadIdx.x;
    const int tx  = tid & 15;
    const int ty  = tid >> 4;
    const int m0  = blockIdx.y * 128;
    const int n0  = blockIdx.x * 64;

    const float* X = (MODE == 0) ? Xin : (const float*)g_ctx;
    float* Y;
    if (MODE == 0) {
        Y = (which == 0) ? g_qh : (which == 1) ? g_kh : g_vh;
    } else {
        Y = Yout;
    }

    float acc[8][4];
#pragma unroll
    for (int a = 0; a < 8; a++)
#pragma unroll
        for (int b = 0; b < 4; b++) acc[a][b] = 0.f;

    for (int kt = 0; kt < 512; kt += 32) {
#pragma unroll
        for (int i = 0; i < 4; i++) {
            int t = tid + i*256;
            int r = t >> 3, c = (t & 7) * 4;
            float4 v = *reinterpret_cast<const float4*>(X + (size_t)(m0 + r)*512 + kt + c);
            Xs[r*33+c+0] = v.x; Xs[r*33+c+1] = v.y; Xs[r*33+c+2] = v.z; Xs[r*33+c+3] = v.w;
        }
#pragma unroll
        for (int i = 0; i < 2; i++) {
            int t = tid + i*256;
            int r = t >> 3, c = (t & 7) * 4;
            float4 v = *reinterpret_cast<const float4*>(W + (size_t)(n0 + r)*512 + kt + c);
            Ws[r*33+c+0] = v.x; Ws[r*33+c+1] = v.y; Ws[r*33+c+2] = v.z; Ws[r*33+c+3] = v.w;
        }
        __syncthreads();
#pragma unroll
        for (int k = 0; k < 32; k++) {
            float xr[8], wr[4];
#pragma unroll
            for (int a = 0; a < 8; a++) xr[a] = Xs[(ty + 16*a)*33 + k];
#pragma unroll
            for (int b = 0; b < 4; b++) wr[b] = Ws[(tx + 16*b)*33 + k];
#pragma unroll
            for (int a = 0; a < 8; a++)
#pragma unroll
                for (int b = 0; b < 4; b++) acc[a][b] += xr[a] * wr[b];
        }
        __syncthreads();
    }

#pragma unroll
    for (int b = 0; b < 4; b++) {
        int col = n0 + tx + 16*b;
        float bv = bias[col];
#pragma unroll
        for (int a = 0; a < 8; a++) {
            int row = m0 + ty + 16*a;
            float v = acc[a][b] + bv;
            if (MODE == 0) {
                int bb = row >> 11;       // row / 2048
                int l  = row & 2047;
                int h  = col >> 6;        // col / 64
                int dh = col & 63;
                Y[(((size_t)bb*HH + h)*LL + l)*DHH + dh] = v;
            } else {
                Y[(size_t)row*512 + col] = v;
            }
        }
    }
}

// ---------------------------------------------------------------------------
// Fused causal attention with relative-position skew.
//   logits[i,j] = (q_i.k_j + (j<=i ? q_i.E[2047-i+j] : 0)) / 8,  causal mask.
// Phase 1: per 64x64 tile compute S_qk (64x64) and QE band (64x128),
//          combine via band lookup, online row max/sum, spill raw logits.
// Phase 2: reload own logits, normalize -> final attn, accumulate P@V.
// Block = one (b*H+h, 64-row tile). 256 threads, 16x16 layout.
// ---------------------------------------------------------------------------
__global__ __launch_bounds__(256) void attn_kernel(
    const float* __restrict__ E,
    float* __restrict__ attn)   // [BH, L, L] region inside d_out
{
    extern __shared__ float sm[];
    float* Qs = sm;           // 64*65  (phase2: V tile)
    float* Ks = sm + 4160;    // 64*65  (phase2: P tile)
    float* Es = sm + 8320;    // 128*65 (reused as QE band 64*130)

    const int tid = threadIdx.x;
    const int tx  = tid & 15;
    const int ty  = tid >> 4;
    const int bi  = 31 - (int)blockIdx.x;   // heavy tiles launch first
    const int bh  = blockIdx.y;
    const int i0  = bi * 64;
    const size_t hbase = (size_t)bh * LL * DHH;
    float* attn_h = attn + (size_t)bh * LL * LL;

    {   // Q tile -> smem
        const float* src = g_qh + hbase + (size_t)i0 * DHH;
#pragma unroll
        for (int i = 0; i < 4; i++) {
            int t = tid + i*256;
            int r = t >> 4, c = (t & 15) * 4;
            float4 v = *reinterpret_cast<const float4*>(src + r*64 + c);
            Qs[r*65+c+0] = v.x; Qs[r*65+c+1] = v.y; Qs[r*65+c+2] = v.z; Qs[r*65+c+3] = v.w;
        }
    }

    float mrow[4], srow[4];
#pragma unroll
    for (int a = 0; a < 4; a++) { mrow[a] = -INFINITY; srow[a] = 0.f; }

    // ---------------- Phase 1 ----------------
    for (int tj = 0; tj <= bi; tj++) {
        const int j0 = tj * 64;
        __syncthreads();
        {   // K tile
            const float* src = g_kh + hbase + (size_t)j0 * DHH;
#pragma unroll
            for (int i = 0; i < 4; i++) {
                int t = tid + i*256;
                int r = t >> 4, c = (t & 15) * 4;
                float4 v = *reinterpret_cast<const float4*>(src + r*64 + c);
                Ks[r*65+c+0] = v.x; Ks[r*65+c+1] = v.y; Ks[r*65+c+2] = v.z; Ks[r*65+c+3] = v.w;
            }
        }
        {   // E band: 128 rows from base_e (clamped rows only feed masked entries)
            int base_e = 1984 - i0 + j0;
#pragma unroll
            for (int i = 0; i < 8; i++) {
                int t = tid + i*256;
                int r = t >> 4, c = (t & 15) * 4;
                int er = base_e + r; er = er > 2047 ? 2047 : er;
                float4 v = *reinterpret_cast<const float4*>(E + (size_t)er*64 + c);
                Es[r*65+c+0] = v.x; Es[r*65+c+1] = v.y; Es[r*65+c+2] = v.z; Es[r*65+c+3] = v.w;
            }
        }
        __syncthreads();

        float aqk[4][4], aqe[4][8];
#pragma unroll
        for (int a = 0; a < 4; a++) {
#pragma unroll
            for (int b = 0; b < 4; b++) aqk[a][b] = 0.f;
#pragma unroll
            for (int c = 0; c < 8; c++) aqe[a][c] = 0.f;
        }
#pragma unroll 8
        for (int k = 0; k < 64; k++) {
            float qr[4];
#pragma unroll
            for (int a = 0; a < 4; a++) qr[a] = Qs[(ty + 16*a)*65 + k];
#pragma unroll
            for (int b = 0; b < 4; b++) {
                float kr = Ks[(tx + 16*b)*65 + k];
#pragma unroll
                for (int a = 0; a < 4; a++) aqk[a][b] += qr[a] * kr;
            }
#pragma unroll
            for (int c = 0; c < 8; c++) {
                float er = Es[(tx + 16*c)*65 + k];
#pragma unroll
                for (int a = 0; a < 4; a++) aqe[a][c] += qr[a] * er;
            }
        }
        __syncthreads();
#pragma unroll
        for (int a = 0; a < 4; a++)
#pragma unroll
            for (int c = 0; c < 8; c++)
                Es[(ty + 16*a)*130 + tx + 16*c] = aqe[a][c];
        __syncthreads();

#pragma unroll
        for (int a = 0; a < 4; a++) {
            int row = ty + 16*a;
            int i   = i0 + row;
            float l[4];
            float lmax = -INFINITY;
#pragma unroll
            for (int b = 0; b < 4; b++) {
                int col = tx + 16*b;
                int j   = j0 + col;
                float v = (aqk[a][b] + Es[row*130 + 63 - row + col]) * 0.125f;
                attn_h[(size_t)i * LL + j] = v;           // raw logit spill
                l[b] = (j <= i) ? v : -INFINITY;
                lmax = fmaxf(lmax, l[b]);
            }
#pragma unroll
            for (int o = 8; o > 0; o >>= 1)
                lmax = fmaxf(lmax, __shfl_xor_sync(0xffffffffu, lmax, o, 16));
            float mnew = fmaxf(mrow[a], lmax);
            float corr = __expf(mrow[a] - mnew);
            float ss = 0.f;
#pragma unroll
            for (int b = 0; b < 4; b++) ss += __expf(l[b] - mnew);
#pragma unroll
            for (int o = 8; o > 0; o >>= 1)
                ss += __shfl_xor_sync(0xffffffffu, ss, o, 16);
            srow[a] = srow[a]*corr + ss;
            mrow[a] = mnew;
        }
    }

    float isr[4];
#pragma unroll
    for (int a = 0; a < 4; a++) isr[a] = 1.f / srow[a];

    // ---------------- Phase 2 ----------------
    for (int tj = bi + 1; tj < 32; tj++) {   // zero future tiles
        float* dst = attn_h + (size_t)i0 * LL + tj*64;
        for (int t = tid; t < 1024; t += 256) {
            int r = t >> 4, c = (t & 15) * 4;
            float4 z = make_float4(0.f, 0.f, 0.f, 0.f);
            *reinterpret_cast<float4*>(dst + (size_t)r * LL + c) = z;
        }
    }

    float acc_o[4][4];
#pragma unroll
    for (int a = 0; a < 4; a++)
#pragma unroll
        for (int b = 0; b < 4; b++) acc_o[a][b] = 0.f;

    for (int tj = 0; tj <= bi; tj++) {
        const int j0 = tj * 64;
        __syncthreads();
        {   // V tile into Qs region
            const float* src = g_vh + hbase + (size_t)j0 * DHH;
#pragma unroll
            for (int i = 0; i < 4; i++) {
                int t = tid + i*256;
                int r = t >> 4, c = (t & 15) * 4;
                float4 v = *reinterpret_cast<const float4*>(src + r*64 + c);
                Qs[r*65+c+0] = v.x; Qs[r*65+c+1] = v.y; Qs[r*65+c+2] = v.z; Qs[r*65+c+3] = v.w;
            }
        }
#pragma unroll
        for (int a = 0; a < 4; a++) {
            int row = ty + 16*a;
            int i   = i0 + row;
#pragma unroll
            for (int b = 0; b < 4; b++) {
                int col = tx + 16*b;
                int j   = j0 + col;
                float v = attn_h[(size_t)i * LL + j];
                float p = (j <= i) ? __expf(v - mrow[a]) * isr[a] : 0.f;
                attn_h[(size_t)i * LL + j] = p;
                Ks[row*65 + col] = p;
            }
        }
        __syncthreads();
#pragma unroll 8
        for (int k = 0; k < 64; k++) {
            float pr[4], vr[4];
#pragma unroll
            for (int a = 0; a < 4; a++) pr[a] = Ks[(ty + 16*a)*65 + k];
#pragma unroll
            for (int b = 0; b < 4; b++) vr[b] = Qs[k*65 + tx + 16*b];
#pragma unroll
            for (int a = 0; a < 4; a++)
#pragma unroll
                for (int b = 0; b < 4; b++) acc_o[a][b] += pr[a] * vr[b];
        }
    }

    const int b_ = bh >> 3;
    const int h  = bh & 7;
#pragma unroll
    for (int a = 0; a < 4; a++) {
        int row = i0 + ty + 16*a;
#pragma unroll
        for (int b = 0; b < 4; b++) {
            int col = h*64 + tx + 16*b;
            g_ctx[((size_t)b_ * LL + row) * DD + col] = acc_o[a][b];
        }
    }
}

// ---------------------------------------------------------------------------
extern "C" void kernel_launch(void* const* d_in, const int* in_sizes, int n_in,
                              void* d_out, int out_size)
{
    (void)in_sizes; (void)n_in; (void)out_size;
    const float* q    = (const float*)d_in[0];
    const float* k    = (const float*)d_in[1];
    const float* v    = (const float*)d_in[2];
    const float* Wq_w = (const float*)d_in[3];
    const float* Wq_b = (const float*)d_in[4];
    const float* Wk_w = (const float*)d_in[5];
    const float* Wk_b = (const float*)d_in[6];
    const float* Wv_w = (const float*)d_in[7];
    const float* Wv_b = (const float*)d_in[8];
    const float* fc_w = (const float*)d_in[9];
    const float* fc_b = (const float*)d_in[10];
    const float* E    = (const float*)d_in[11];
    // d_in[12] = mask (deterministic causal triu; folded into the kernel)

    float* out  = (float*)d_out;                       // [B, L, D]
    float* attn = out + (size_t)BB * LL * DD;          // [B, H, L, L]

    const int attn_smem = 16640 * 4;  // 66,560 B dynamic shared
    cudaFuncSetAttribute(attn_kernel,
                         cudaFuncAttributeMaxDynamicSharedMemorySize, attn_smem);

    dim3 gthr(256);
    dim3 ggrid(512/64, 4096/128);   // (8, 32)

    gemm_bias_kernel<0><<<ggrid, gthr>>>(q, Wq_w, Wq_b, nullptr, 0);
    gemm_bias_kernel<0><<<ggrid, gthr>>>(k, Wk_w, Wk_b, nullptr, 1);
    gemm_bias_kernel<0><<<ggrid, gthr>>>(v, Wv_w, Wv_b, nullptr, 2);

    attn_kernel<<<dim3(32, BHH), 256, attn_smem>>>(E, attn);

    gemm_bias_kernel<1><<<ggrid, gthr>>>(nullptr, fc_w, fc_b, out, 0);
}

// round 4
// speedup vs baseline: 1.4756x; 1.4756x over previous
#include <cuda_runtime.h>
#include <math.h>
#include <stdint.h>

#define BB 2
#define LL 2048
#define DD 512
#define HH 8
#define DHH 64
#define BHH (BB*HH)

// Scratch (allocation-free rule: __device__ globals referenced from device code)
__device__ float g_qh[BHH*LL*DHH];
__device__ float g_kh[BHH*LL*DHH];
__device__ float g_vh[BHH*LL*DHH];
__device__ float g_ctx[BB*LL*DD];

// ---------------------------------------------------------------------------
// GEMM: Y = X @ W^T + bias.  (unchanged from the passing R3 kernel)
// MODE 0: X from param, scatter into g_qh/g_kh/g_vh per `which`
// MODE 1: X = g_ctx (device global), plain row-major into Y
// ---------------------------------------------------------------------------
template<int MODE>
__global__ __launch_bounds__(256) void gemm_bias_kernel(
    const float* __restrict__ Xin, const float* __restrict__ W,
    const float* __restrict__ bias, float* __restrict__ Yout, int which)
{
    __shared__ float Xs[128*33];
    __shared__ float Ws[64*33];
    const int tid = threadIdx.x;
    const int tx  = tid & 15;
    const int ty  = tid >> 4;
    const int m0  = blockIdx.y * 128;
    const int n0  = blockIdx.x * 64;

    const float* X = (MODE == 0) ? Xin : (const float*)g_ctx;
    float* Y;
    if (MODE == 0) {
        Y = (which == 0) ? g_qh : (which == 1) ? g_kh : g_vh;
    } else {
        Y = Yout;
    }

    float acc[8][4];
#pragma unroll
    for (int a = 0; a < 8; a++)
#pragma unroll
        for (int b = 0; b < 4; b++) acc[a][b] = 0.f;

    for (int kt = 0; kt < 512; kt += 32) {
#pragma unroll
        for (int i = 0; i < 4; i++) {
            int t = tid + i*256;
            int r = t >> 3, c = (t & 7) * 4;
            float4 v = *reinterpret_cast<const float4*>(X + (size_t)(m0 + r)*512 + kt + c);
            Xs[r*33+c+0] = v.x; Xs[r*33+c+1] = v.y; Xs[r*33+c+2] = v.z; Xs[r*33+c+3] = v.w;
        }
#pragma unroll
        for (int i = 0; i < 2; i++) {
            int t = tid + i*256;
            int r = t >> 3, c = (t & 7) * 4;
            float4 v = *reinterpret_cast<const float4*>(W + (size_t)(n0 + r)*512 + kt + c);
            Ws[r*33+c+0] = v.x; Ws[r*33+c+1] = v.y; Ws[r*33+c+2] = v.z; Ws[r*33+c+3] = v.w;
        }
        __syncthreads();
#pragma unroll
        for (int k = 0; k < 32; k++) {
            float xr[8], wr[4];
#pragma unroll
            for (int a = 0; a < 8; a++) xr[a] = Xs[(ty + 16*a)*33 + k];
#pragma unroll
            for (int b = 0; b < 4; b++) wr[b] = Ws[(tx + 16*b)*33 + k];
#pragma unroll
            for (int a = 0; a < 8; a++)
#pragma unroll
                for (int b = 0; b < 4; b++) acc[a][b] += xr[a] * wr[b];
        }
        __syncthreads();
    }

#pragma unroll
    for (int b = 0; b < 4; b++) {
        int col = n0 + tx + 16*b;
        float bv = bias[col];
#pragma unroll
        for (int a = 0; a < 8; a++) {
            int row = m0 + ty + 16*a;
            float v = acc[a][b] + bv;
            if (MODE == 0) {
                int bb = row >> 11;
                int l  = row & 2047;
                int h  = col >> 6;
                int dh = col & 63;
                Y[(((size_t)bb*HH + h)*LL + l)*DHH + dh] = v;
            } else {
                Y[(size_t)row*512 + col] = v;
            }
        }
    }
}

// ---------------------------------------------------------------------------
// tf32 mma helpers
// ---------------------------------------------------------------------------
__device__ __forceinline__ uint32_t f2tf32(float f) {
    uint32_t u;
    asm("cvt.rna.tf32.f32 %0, %1;" : "=r"(u) : "f"(f));
    return u;
}

__device__ __forceinline__ void mma_tf32(float c[4],
    uint32_t a0, uint32_t a1, uint32_t a2, uint32_t a3,
    uint32_t b0, uint32_t b1)
{
    asm volatile(
        "mma.sync.aligned.m16n8k8.row.col.f32.tf32.tf32.f32 "
        "{%0,%1,%2,%3}, {%4,%5,%6,%7}, {%8,%9}, {%0,%1,%2,%3};"
        : "+f"(c[0]), "+f"(c[1]), "+f"(c[2]), "+f"(c[3])
        : "r"(a0), "r"(a1), "r"(a2), "r"(a3), "r"(b0), "r"(b1));
}

// ---------------------------------------------------------------------------
// Fused causal attention with relative-position skew — tf32 tensor-core path.
//   logits[i,j] = (q_i.k_j + (j<=i ? q_i.E[2047-i+j] : 0)) / 8,  causal mask.
// Phase 1: per 64x64 tile compute S=QK^T (64x64) and T=Q.Eband^T (64x128)
//          via mma.m16n8k8.tf32; combine with skew lookup; online row max/sum
//          in smem; spill raw fp32 logits into the attn output region.
// Phase 2: reload own logits, normalize -> final attn, PV via mma.
// Block = one (b*H+h, 64-row tile). 256 threads = 8 warps:
//   warp w: rg = w&3 (rows rg*16..+15), cs = w>>2 (col half).
// Smem strides: 68 (==4 mod 32) for row-major A/B quad loads,
//               72 (==8 mod 32) for transposed V B loads — conflict-free.
// ---------------------------------------------------------------------------
#define QS_OFF 0
#define KS_OFF 4352
#define ES_OFF 8704
#define MS_OFF 17408
#define SS_OFF 17472
#define PM_OFF 17536
#define PSUM_OFF 17664
#define SMEM_FLOATS 17792

__global__ __launch_bounds__(256) void attn_kernel(
    const float* __restrict__ E,
    float* __restrict__ attn)   // [BH, L, L] region inside d_out
{
    extern __shared__ float sm[];
    float* Qs  = sm + QS_OFF;    // 64 x 68 (tf32)
    float* Ks  = sm + KS_OFF;    // 64 x 68 (tf32)  | phase2: P 64x68 (tf32)
    float* Es  = sm + ES_OFF;    // 128 x 68 (tf32) | band 64x130 fp32 | phase2: V 64x72 (tf32)
    float* m_s = sm + MS_OFF;    // [64]
    float* s_s = sm + SS_OFF;    // [64]
    float* pm  = sm + PM_OFF;    // [2][64]
    float* psd = sm + PSUM_OFF;  // [2][64]

    const int tid  = threadIdx.x;
    const int lane = tid & 31;
    const int w    = tid >> 5;
    const int rg   = w & 3;
    const int cs   = w >> 2;
    const int r0   = rg * 16;
    const int qr   = lane >> 2;   // 0..7
    const int qc   = lane & 3;    // 0..3

    const int bi = 31 - (int)blockIdx.x;   // heavy tiles launch first
    const int bh = blockIdx.y;
    const int i0 = bi * 64;
    const size_t hbase = (size_t)bh * LL * DHH;
    float* attn_h = attn + (size_t)bh * LL * LL;

    if (tid < 64) { m_s[tid] = -INFINITY; s_s[tid] = 0.f; }

    {   // Q tile -> Qs (tf32, stride 68)
        const float* src = g_qh + hbase + (size_t)i0 * DHH;
#pragma unroll
        for (int it = 0; it < 4; it++) {
            int t = tid + it*256;
            int r = t >> 4, c = (t & 15) * 4;
            float4 v = *reinterpret_cast<const float4*>(src + r*64 + c);
            Qs[r*68+c+0] = __uint_as_float(f2tf32(v.x));
            Qs[r*68+c+1] = __uint_as_float(f2tf32(v.y));
            Qs[r*68+c+2] = __uint_as_float(f2tf32(v.z));
            Qs[r*68+c+3] = __uint_as_float(f2tf32(v.w));
        }
    }

    // ---------------- Phase 1 ----------------
    for (int tj = 0; tj <= bi; tj++) {
        const int j0 = tj * 64;
        __syncthreads();   // protect Ks/Es (band) from prev-iter readers
        {   // K tile -> Ks (tf32)
            const float* src = g_kh + hbase + (size_t)j0 * DHH;
#pragma unroll
            for (int it = 0; it < 4; it++) {
                int t = tid + it*256;
                int r = t >> 4, c = (t & 15) * 4;
                float4 v = *reinterpret_cast<const float4*>(src + r*64 + c);
                Ks[r*68+c+0] = __uint_as_float(f2tf32(v.x));
                Ks[r*68+c+1] = __uint_as_float(f2tf32(v.y));
                Ks[r*68+c+2] = __uint_as_float(f2tf32(v.z));
                Ks[r*68+c+3] = __uint_as_float(f2tf32(v.w));
            }
        }
        {   // E band: 128 rows from base_e (clamped rows only feed masked entries)
            int base_e = 1984 - i0 + j0;
#pragma unroll
            for (int it = 0; it < 8; it++) {
                int t = tid + it*256;
                int r = t >> 4, c = (t & 15) * 4;
                int er = base_e + r; er = er > 2047 ? 2047 : er;
                float4 v = *reinterpret_cast<const float4*>(E + (size_t)er*64 + c);
                Es[r*68+c+0] = __uint_as_float(f2tf32(v.x));
                Es[r*68+c+1] = __uint_as_float(f2tf32(v.y));
                Es[r*68+c+2] = __uint_as_float(f2tf32(v.z));
                Es[r*68+c+3] = __uint_as_float(f2tf32(v.w));
            }
        }
        __syncthreads();

        float sacc[4][4], tacc[8][4];
#pragma unroll
        for (int t = 0; t < 4; t++)
#pragma unroll
            for (int e = 0; e < 4; e++) sacc[t][e] = 0.f;
#pragma unroll
        for (int t = 0; t < 8; t++)
#pragma unroll
            for (int e = 0; e < 4; e++) tacc[t][e] = 0.f;

#pragma unroll
        for (int kk = 0; kk < 64; kk += 8) {
            uint32_t a0 = __float_as_uint(Qs[(r0+qr  )*68 + kk + qc    ]);
            uint32_t a1 = __float_as_uint(Qs[(r0+qr+8)*68 + kk + qc    ]);
            uint32_t a2 = __float_as_uint(Qs[(r0+qr  )*68 + kk + qc + 4]);
            uint32_t a3 = __float_as_uint(Qs[(r0+qr+8)*68 + kk + qc + 4]);
#pragma unroll
            for (int t = 0; t < 4; t++) {
                int n0 = cs*32 + t*8;
                uint32_t b0 = __float_as_uint(Ks[(n0+qr)*68 + kk + qc    ]);
                uint32_t b1 = __float_as_uint(Ks[(n0+qr)*68 + kk + qc + 4]);
                mma_tf32(sacc[t], a0, a1, a2, a3, b0, b1);
            }
#pragma unroll
            for (int t = 0; t < 8; t++) {
                int n0 = cs*64 + t*8;
                uint32_t b0 = __float_as_uint(Es[(n0+qr)*68 + kk + qc    ]);
                uint32_t b1 = __float_as_uint(Es[(n0+qr)*68 + kk + qc + 4]);
                mma_tf32(tacc[t], a0, a1, a2, a3, b0, b1);
            }
        }
        __syncthreads();   // all warps done reading Es as E-tiles

        // write QE band (raw fp32) into Es region, stride 130
#pragma unroll
        for (int t = 0; t < 8; t++) {
            int colT = cs*64 + t*8 + 2*qc;
            Es[(r0+qr  )*130 + colT    ] = tacc[t][0];
            Es[(r0+qr  )*130 + colT + 1] = tacc[t][1];
            Es[(r0+qr+8)*130 + colT    ] = tacc[t][2];
            Es[(r0+qr+8)*130 + colT + 1] = tacc[t][3];
        }
        __syncthreads();

        // epilogue: combine skew, spill logits, per-row partial max/sum
#pragma unroll
        for (int h = 0; h < 2; h++) {
            int row = r0 + qr + 8*h;
            int i   = i0 + row;
            float l[8];
            float lmax = -INFINITY;
#pragma unroll
            for (int t = 0; t < 4; t++) {
#pragma unroll
                for (int e = 0; e < 2; e++) {
                    int col = cs*32 + t*8 + 2*qc + e;
                    int j   = j0 + col;
                    float v = (sacc[t][2*h+e] + Es[row*130 + 63 - row + col]) * 0.125f;
                    attn_h[(size_t)i * LL + j] = v;      // raw logit spill
                    float lv = (j <= i) ? v : -INFINITY;
                    l[t*2+e] = lv;
                    lmax = fmaxf(lmax, lv);
                }
            }
            lmax = fmaxf(lmax, __shfl_xor_sync(0xffffffffu, lmax, 1));
            lmax = fmaxf(lmax, __shfl_xor_sync(0xffffffffu, lmax, 2));
            float ss = 0.f;
            if (lmax > -INFINITY) {
#pragma unroll
                for (int x = 0; x < 8; x++) ss += __expf(l[x] - lmax);
            }
            ss += __shfl_xor_sync(0xffffffffu, ss, 1);
            ss += __shfl_xor_sync(0xffffffffu, ss, 2);
            if (qc == 0) { pm[cs*64 + row] = lmax; psd[cs*64 + row] = ss; }
        }
        __syncthreads();
        if (tid < 64) {
            float m0v = pm[tid], m1v = pm[64 + tid];
            float lm   = fmaxf(m0v, m1v);
            float mold = m_s[tid];
            float mnew = fmaxf(mold, lm);
            float sa = s_s[tid] * __expf(mold - mnew);
            float s0 = (m0v > -INFINITY) ? psd[tid]      * __expf(m0v - mnew) : 0.f;
            float s1 = (m1v > -INFINITY) ? psd[64 + tid] * __expf(m1v - mnew) : 0.f;
            s_s[tid] = sa + s0 + s1;
            m_s[tid] = mnew;
        }
    }
    __syncthreads();

    // ---------------- Phase 2 ----------------
    // zero fully-masked (future) tiles
    for (int tj = bi + 1; tj < 32; tj++) {
        float* dst = attn_h + (size_t)i0 * LL + tj*64;
        for (int t = tid; t < 1024; t += 256) {
            int r = t >> 4, c = (t & 15) * 4;
            float4 z = make_float4(0.f, 0.f, 0.f, 0.f);
            *reinterpret_cast<float4*>(dst + (size_t)r * LL + c) = z;
        }
    }

    const int tx = tid & 15, ty = tid >> 4;
    float mrow[4], isr[4];
#pragma unroll
    for (int a = 0; a < 4; a++) {
        mrow[a] = m_s[ty + 16*a];
        isr[a]  = 1.f / s_s[ty + 16*a];
    }

    float oacc[4][4];
#pragma unroll
    for (int t = 0; t < 4; t++)
#pragma unroll
        for (int e = 0; e < 4; e++) oacc[t][e] = 0.f;

    for (int tj = 0; tj <= bi; tj++) {
        const int j0 = tj * 64;
        __syncthreads();   // protect Vs/Ps from prev-iter mma reads
        {   // V tile -> Es region, stride 72 (tf32)
            const float* src = g_vh + hbase + (size_t)j0 * DHH;
#pragma unroll
            for (int it = 0; it < 4; it++) {
                int t = tid + it*256;
                int r = t >> 4, c = (t & 15) * 4;
                float4 v = *reinterpret_cast<const float4*>(src + r*64 + c);
                Es[r*72+c+0] = __uint_as_float(f2tf32(v.x));
                Es[r*72+c+1] = __uint_as_float(f2tf32(v.y));
                Es[r*72+c+2] = __uint_as_float(f2tf32(v.z));
                Es[r*72+c+3] = __uint_as_float(f2tf32(v.w));
            }
        }
        // reload own logits -> normalized p -> attn + Ps (Ks region, tf32)
#pragma unroll
        for (int a = 0; a < 4; a++) {
            int row = ty + 16*a;
            int i   = i0 + row;
#pragma unroll
            for (int b = 0; b < 4; b++) {
                int col = tx + 16*b;
                int j   = j0 + col;
                float v = attn_h[(size_t)i * LL + j];
                float p = (j <= i) ? __expf(v - mrow[a]) * isr[a] : 0.f;
                attn_h[(size_t)i * LL + j] = p;
                Ks[row*68 + col] = __uint_as_float(f2tf32(p));
            }
        }
        __syncthreads();

        // O += P @ V  (A = P row-major from Ks/68, B = V col-major from Es/72)
#pragma unroll
        for (int kk = 0; kk < 64; kk += 8) {
            uint32_t a0 = __float_as_uint(Ks[(r0+qr  )*68 + kk + qc    ]);
            uint32_t a1 = __float_as_uint(Ks[(r0+qr+8)*68 + kk + qc    ]);
            uint32_t a2 = __float_as_uint(Ks[(r0+qr  )*68 + kk + qc + 4]);
            uint32_t a3 = __float_as_uint(Ks[(r0+qr+8)*68 + kk + qc + 4]);
#pragma unroll
            for (int t = 0; t < 4; t++) {
                int n0 = cs*32 + t*8;
                uint32_t b0 = __float_as_uint(Es[(kk+qc  )*72 + n0 + qr]);
                uint32_t b1 = __float_as_uint(Es[(kk+qc+4)*72 + n0 + qr]);
                mma_tf32(oacc[t], a0, a1, a2, a3, b0, b1);
            }
        }
    }

    // write context in (b, l, D) layout for the fc GEMM (fragment layout)
    const int b_ = bh >> 3;
    const int hh = bh & 7;
#pragma unroll
    for (int t = 0; t < 4; t++) {
#pragma unroll
        for (int h = 0; h < 2; h++) {
#pragma unroll
            for (int e = 0; e < 2; e++) {
                int row = i0 + r0 + qr + 8*h;
                int col = hh*64 + cs*32 + t*8 + 2*qc + e;
                g_ctx[((size_t)b_ * LL + row) * DD + col] = oacc[t][2*h+e];
            }
        }
    }
}

// ---------------------------------------------------------------------------
extern "C" void kernel_launch(void* const* d_in, const int* in_sizes, int n_in,
                              void* d_out, int out_size)
{
    (void)in_sizes; (void)n_in; (void)out_size;
    const float* q    = (const float*)d_in[0];
    const float* k    = (const float*)d_in[1];
    const float* v    = (const float*)d_in[2];
    const float* Wq_w = (const float*)d_in[3];
    const float* Wq_b = (const float*)d_in[4];
    const float* Wk_w = (const float*)d_in[5];
    const float* Wk_b = (const float*)d_in[6];
    const float* Wv_w = (const float*)d_in[7];
    const float* Wv_b = (const float*)d_in[8];
    const float* fc_w = (const float*)d_in[9];
    const float* fc_b = (const float*)d_in[10];
    const float* E    = (const float*)d_in[11];
    // d_in[12] = mask (deterministic causal triu; folded into the kernel)

    float* out  = (float*)d_out;                       // [B, L, D]
    float* attn = out + (size_t)BB * LL * DD;          // [B, H, L, L]

    const int attn_smem = SMEM_FLOATS * 4;             // 71,168 B dynamic shared
    cudaFuncSetAttribute(attn_kernel,
                         cudaFuncAttributeMaxDynamicSharedMemorySize, attn_smem);

    dim3 gthr(256);
    dim3 ggrid(512/64, 4096/128);   // (8, 32)

    gemm_bias_kernel<0><<<ggrid, gthr>>>(q, Wq_w, Wq_b, nullptr, 0);
    gemm_bias_kernel<0><<<ggrid, gthr>>>(k, Wk_w, Wk_b, nullptr, 1);
    gemm_bias_kernel<0><<<ggrid, gthr>>>(v, Wv_w, Wv_b, nullptr, 2);

    attn_kernel<<<dim3(32, BHH), 256, attn_smem>>>(E, attn);

    gemm_bias_kernel<1><<<ggrid, gthr>>>(nullptr, fc_w, fc_b, out, 0);
}